// round 12
// baseline (speedup 1.0000x reference)
#include <cuda_runtime.h>
#include <cuda_fp16.h>

#define TN 400
#define PN 4000
#define NBLOCKS 152       // one block per GB300 SM
#define TPB 800           // 25 warps x 16 targets = 400, all lanes active
#define MAXPAIR 14        // >= ceil(ceil(PN/NBLOCKS)/2)
#define PROW 80           // 32-bit slots per PRED-PAIR row

// dynamic smem layout (floats):
//   stg  [0 .. 21200)                staged tkp (400 x 53), fp32
//   sraw [21200 .. 21200+1488)       staged raw pred rows, fp32
//   ptile[22688 .. +MAXPAIR*PROW)    pred-PAIR rows (half2 packed + fp32 scalars)
#define STG_OFF   0
#define SRAW_OFF  21200
#define PTILE_OFF (21200 + 1488)
#define SMEM_FLOATS (PTILE_OFF + MAXPAIR * PROW)
#define SMEM_BYTES  (SMEM_FLOATS * 4)

// pair row (80 x 32-bit slots); half2 = {value of pred A, value of pred B}
//   u[ 0.. 8] x of kp0..8     u[ 9..11] 0
//   u[12..20] y of kp0..8     u[21..23] 0
//   u[24..32] x of kp9..16(+0) u[33..35] 0
//   u[36..44] y of kp9..16(+0) u[45..47] 0
//   u[48..56] Vp kp0..8        u[57..59] 0
//   u[60..68] Vp kp9..16(+0)   u[69..71] 0
//   f[72..75] pred A: {cp0, cp1, p0-p1, spp}
//   f[76..79] pred B: {cp0, cp1, p0-p1, spp}

__device__ __forceinline__ __half2 u2h(unsigned u) {
    __half2 h; *reinterpret_cast<unsigned*>(&h) = u; return h;
}
__device__ __forceinline__ unsigned h2u(__half2 h) {
    return *reinterpret_cast<unsigned*>(&h);
}

__global__ __launch_bounds__(TPB, 1)
void matcher_kernel(const float* __restrict__ logits,   // [PN,2]
                    const float* __restrict__ pkp,      // [PN,53]
                    const int*   __restrict__ tids,     // [TN]
                    const float* __restrict__ tkp,      // [TN,53]
                    const int*   __restrict__ nbp,      // scalar num_boxes
                    float*       __restrict__ out)      // [PN,TN]
{
    extern __shared__ __align__(16) float dsm[];
    float* stg   = dsm + STG_OFF;
    float* sraw  = dsm + SRAW_OFF;
    float* ptile = dsm + PTILE_OFF;

    const int b = blockIdx.x;
    const int pbase = (b * PN) / NBLOCKS;
    const int npred = ((b + 1) * PN) / NBLOCKS - pbase;
    const int npair = (npred + 1) >> 1;
    const int tid  = threadIdx.x;
    const int lane = tid & 31;
    const int h    = lane >> 4;                       // keypoint half
    const int tw   = ((tid >> 5) << 4) | (lane & 15); // target 0..399

    int nbi = *nbp;
    float nb = (nbi > 0 && nbi < (1 << 20)) ? (float)nbi : *(const float*)nbp;
    const float inb = 1.0f / nb;

    // ---- coalesced staging: targets (float4) + this block's raw preds ----
    {
        const float4* src = (const float4*)tkp;       // 21200 floats = 5300 float4
        float4* dst = (float4*)stg;
        #pragma unroll
        for (int i = 0; i < 7; ++i) {
            int idx = tid + i * TPB;
            if (idx < 5300) dst[idx] = src[idx];
        }
        const int nraw = npred * 53;
        const float* ps = pkp + pbase * 53;
        for (int i = tid; i < nraw; i += TPB) sraw[i] = ps[i];
    }
    __syncthreads();

    // ---- pair-row fill (fp32 -> packed half2), parallel across all threads ----
    {
        const int total = npair * PROW;
        for (int idx = tid; idx < total; idx += TPB) {
            const int pr = idx / PROW;
            const int s  = idx - pr * PROW;
            if (s >= 72) continue;                     // fp32 scalar slots
            const int pa = 2 * pr;
            const int pb = (2 * pr + 1 < npred) ? 2 * pr + 1 : pa;
            const float* ka = sraw + pa * 53;
            const float* kb = sraw + pb * 53;
            unsigned val = 0u;
            int j;
            if (s < 9)                      { j = s;            val = h2u(__floats2half2_rn(ka[2 + 2*j], kb[2 + 2*j])); }
            else if (s >= 12 && s < 21)     { j = s - 12;       val = h2u(__floats2half2_rn(ka[3 + 2*j], kb[3 + 2*j])); }
            else if (s >= 24 && s < 33)     { j = 9 + s - 24;   if (j < 17) val = h2u(__floats2half2_rn(ka[2 + 2*j], kb[2 + 2*j])); }
            else if (s >= 36 && s < 45)     { j = 9 + s - 36;   if (j < 17) val = h2u(__floats2half2_rn(ka[3 + 2*j], kb[3 + 2*j])); }
            else if (s >= 48 && s < 57)     { j = s - 48;       val = h2u(__floats2half2_rn(ka[36 + j], kb[36 + j])); }
            else if (s >= 60 && s < 69)     { j = 9 + s - 60;   if (j < 17) val = h2u(__floats2half2_rn(ka[36 + j], kb[36 + j])); }
            ((unsigned*)(ptile + pr * PROW))[s] = val;
        }
    }
    // ---- per-pred fp32 scalars (threads 0..npred-1) ----
    if (tid < npred) {
        const int gp = pbase + tid;
        const float l0 = logits[gp * 2 + 0];
        const float l1 = logits[gp * 2 + 1];
        const float m  = fmaxf(l0, l1);
        const float e0 = __expf(l0 - m);
        const float e1 = __expf(l1 - m);
        const float inv = 1.0f / (e0 + e1);
        const float p0 = e0 * inv, p1 = e1 * inv;

        const float* kp = sraw + tid * 53;
        const float c0 = kp[0], c1 = kp[1];
        float sv = 0.0f;
        #pragma unroll
        for (int j = 0; j < 17; ++j) { float v = kp[36 + j]; sv = fmaf(v, v, sv); }
        float* sp = ptile + (tid >> 1) * PROW + 72 + (tid & 1) * 4;
        sp[0] = c0;
        sp[1] = c1;
        sp[2] = p0 - p1;
        sp[3] = 0.2f * inb * sv + 0.5f * inb * (c0 * c0 + c1 * c1) - p0;  // spp
    }

    // ---- per-thread target state (broadcast half2), from staged smem ----
    const float* tk = stg + tw * 53;
    const float cg0 = tk[0], cg1 = tk[1];
    const int jb  = h ? 9 : 0;
    const int cnt = h ? 8 : 9;
    __half2 nzgx[9], nzgy[9];  // {-Zg, -Zg} broadcast
    __half2 w2[9];             // {0.5*inb*Vg, same}
    #pragma unroll
    for (int i = 0; i < 9; ++i) {
        const int j = jb + i;
        const bool ok = (i < cnt);
        float zx = ok ? -tk[2 + 2 * j] : 0.0f;
        float zy = ok ? -tk[3 + 2 * j] : 0.0f;
        float wv = ok ? 0.5f * inb * tk[36 + j] : 0.0f;
        nzgx[i] = __half2half2(__float2half_rn(zx));
        nzgy[i] = __half2half2(__float2half_rn(zy));
        w2[i]   = __half2half2(__float2half_rn(wv));
    }
    const float ncgx = -cg0, ncgy = -cg1;
    float tcx = 0.0f, tcy = 0.0f, idf = 0.0f, sgt = 0.0f, cflag = 0.0f;
    if (h == 0) {
        float sv = 0.0f;
        #pragma unroll
        for (int j = 0; j < 17; ++j) { float v = tk[36 + j]; sv = fmaf(v, v, sv); }
        sgt = 0.2f * inb * sv + 0.5f * inb * (cg0 * cg0 + cg1 * cg1);
        tcx = -inb * cg0;
        tcy = -inb * cg1;
        idf = (float)tids[tw];
        cflag = 1.0f;
    }
    __syncthreads();

    const int xoff = h ? 24 : 0;
    const int yoff = h ? 36 : 12;
    const int voff = h ? 60 : 48;
    const bool doStore = (h == 0);

    for (int pr = 0; pr < npair; ++pr) {
        const float* pp = ptile + pr * PROW;
        const unsigned* ru = (const unsigned*)pp;
        const float4 ha = *(const float4*)(pp + 72);   // pred A scalars
        const float4 hb = *(const float4*)(pp + 76);   // pred B scalars
        const __half2 dcx = __floats2half2_rn(ha.x + ncgx, hb.x + ncgx);
        const __half2 dcy = __floats2half2_rn(ha.y + ncgy, hb.y + ncgy);

        const uint4 xA = *(const uint4*)(ru + xoff);       // x kp0..3
        const uint4 xB = *(const uint4*)(ru + xoff + 4);   // x kp4..7
        const unsigned x8 = ru[xoff + 8];
        const uint4 yA = *(const uint4*)(ru + yoff);
        const uint4 yB = *(const uint4*)(ru + yoff + 4);
        const unsigned y8 = ru[yoff + 8];

        __half2 acc  = __floats2half2_rn(0.0f, 0.0f);  // {predA, predB} offset
        __half2 acc8 = __floats2half2_rn(0.0f, 0.0f);  // {predA, predB} abs
        #define KP(xr, yr, i) do {                                         \
            __half2 dzx = __hadd2(u2h(xr), nzgx[i]);                       \
            __half2 tx  = __hadd2(dzx, dcx);                               \
            __half2 dzy = __hadd2(u2h(yr), nzgy[i]);                       \
            __half2 ty  = __hadd2(dzy, dcy);                               \
            __half2 s   = __hadd2(__habs2(dzx), __habs2(dzy));             \
            __half2 s8  = __hadd2(__habs2(tx),  __habs2(ty));              \
            acc  = __hfma2(s,  w2[i], acc);                                \
            acc8 = __hfma2(s8, w2[i], acc8);                               \
        } while (0)
        KP(xA.x, yA.x, 0); KP(xA.y, yA.y, 1); KP(xA.z, yA.z, 2); KP(xA.w, yA.w, 3);
        KP(xB.x, yB.x, 4); KP(xB.y, yB.y, 5); KP(xB.z, yB.z, 6); KP(xB.w, yB.w, 7);
        KP(x8,   y8,   8);
        #undef KP

        // viz dot, packed {predA, predB}, reusing w2
        const uint4 vA = *(const uint4*)(ru + voff);
        const uint4 vB = *(const uint4*)(ru + voff + 4);
        const unsigned v8 = ru[voff + 8];
        __half2 dv2 = __hmul2(u2h(vA.x), w2[0]);
        dv2 = __hfma2(u2h(vA.y), w2[1], dv2);
        dv2 = __hfma2(u2h(vA.z), w2[2], dv2);
        dv2 = __hfma2(u2h(vA.w), w2[3], dv2);
        dv2 = __hfma2(u2h(vB.x), w2[4], dv2);
        dv2 = __hfma2(u2h(vB.y), w2[5], dv2);
        dv2 = __hfma2(u2h(vB.z), w2[6], dv2);
        dv2 = __hfma2(u2h(vB.w), w2[7], dv2);
        dv2 = __hfma2(u2h(v8),   w2[8], dv2);

        const float2 af  = __half22float2(acc);
        const float2 a8f = __half22float2(acc8);
        const float2 dvf = __half22float2(dv2);

        float ra = fmaf(a8f.x, 8.0f, af.x);       // pred A: 0.5*offset + 4*abs
        ra = fmaf(dvf.x, -0.8f, ra);
        ra = fmaf(ha.x, tcx, ra);
        ra = fmaf(ha.y, tcy, ra);
        ra = fmaf(ha.z, idf, ra);
        ra = fmaf(ha.w, cflag, ra);
        ra += sgt;

        float rb = fmaf(a8f.y, 8.0f, af.y);       // pred B
        rb = fmaf(dvf.y, -0.8f, rb);
        rb = fmaf(hb.x, tcx, rb);
        rb = fmaf(hb.y, tcy, rb);
        rb = fmaf(hb.z, idf, rb);
        rb = fmaf(hb.w, cflag, rb);
        rb += sgt;

        ra += __shfl_xor_sync(0xffffffffu, ra, 16);
        rb += __shfl_xor_sync(0xffffffffu, rb, 16);

        if (doStore) {
            const int pa = pbase + 2 * pr;
            out[(size_t)pa * TN + tw] = ra;
            if (2 * pr + 1 < npred)
                out[(size_t)(pa + 1) * TN + tw] = rb;
        }
    }
}

extern "C" void kernel_launch(void* const* d_in, const int* in_sizes, int n_in,
                              void* d_out, int out_size)
{
    const float* logits = (const float*)d_in[0];   // pred_logits   [8,500,2]
    const float* pkp    = (const float*)d_in[1];   // pred_keypoints[8,500,53]
    const int*   tids   = (const int*)  d_in[2];   // tgt_ids       [400]
    const float* tkp    = (const float*)d_in[3];   // tgt_keypoints [400,53]
    const int*   nbp    = (const int*)  d_in[4];   // num_boxes scalar
    (void)in_sizes; (void)n_in; (void)out_size;

    static int smem_set = 0;
    if (!smem_set) {
        cudaFuncSetAttribute(matcher_kernel,
                             cudaFuncAttributeMaxDynamicSharedMemorySize, SMEM_BYTES);
        smem_set = 1;
    }
    matcher_kernel<<<NBLOCKS, TPB, SMEM_BYTES>>>(logits, pkp, tids, tkp, nbp,
                                                 (float*)d_out);
}